// round 12
// baseline (speedup 1.0000x reference)
#include <cuda_runtime.h>

#define PLANEW   1090            // u64 words per plane: 34*32=1088 +2; 1090 % 16 == 2
#define NTHREADS 256
#define NTILES   512
#define GRIDSZ   296             // 2 x 148 SMs: wave-1 fills every slot
#define PI_F     3.14159265358979323846f

typedef unsigned long long u64;

// ---- packed f32x2 helpers (sm_100+ PTX; ptxas never emits these from C++) ----
__device__ __forceinline__ u64 pk(float a, float b) {
    u64 r; asm("mov.b64 %0, {%1, %2};" : "=l"(r) : "f"(a), "f"(b)); return r;
}
__device__ __forceinline__ float2 upk(u64 v) {
    float2 r; asm("mov.b64 {%0, %1}, %2;" : "=f"(r.x), "=f"(r.y) : "l"(v)); return r;
}
__device__ __forceinline__ u64 swp(u64 v) {
    u64 r;
    asm("{\n\t.reg .b32 lo, hi;\n\tmov.b64 {lo, hi}, %1;\n\tmov.b64 %0, {hi, lo};\n\t}"
        : "=l"(r) : "l"(v));
    return r;
}
__device__ __forceinline__ u64 f2add(u64 a, u64 b) {
    u64 r; asm("add.rn.f32x2 %0, %1, %2;" : "=l"(r) : "l"(a), "l"(b)); return r;
}
__device__ __forceinline__ u64 f2sub(u64 a, u64 b) {
    u64 r; asm("sub.rn.f32x2 %0, %1, %2;" : "=l"(r) : "l"(a), "l"(b)); return r;
}
__device__ __forceinline__ u64 f2mul(u64 a, u64 b) {
    u64 r; asm("mul.rn.f32x2 %0, %1, %2;" : "=l"(r) : "l"(a), "l"(b)); return r;
}
__device__ __forceinline__ u64 f2fma(u64 a, u64 b, u64 c) {
    u64 r; asm("fma.rn.f32x2 %0, %1, %2, %3;" : "=l"(r) : "l"(a), "l"(b), "l"(c)); return r;
}
__device__ __forceinline__ u64 cmul(u64 d, u64 wcc, u64 wss) {
    return f2fma(swp(d), wss, f2mul(d, wcc));
}

__device__ __constant__ float C16c[16] = {
    1.0f, 0.980785280403230449f, 0.923879532511286756f, 0.831469612302545237f,
    0.707106781186547524f, 0.555570233019602225f, 0.382683432365089772f,
    0.195090322016128268f, 0.0f, -0.195090322016128268f, -0.382683432365089772f,
    -0.555570233019602225f, -0.707106781186547524f, -0.831469612302545237f,
    -0.923879532511286756f, -0.980785280403230449f};
__device__ __constant__ float S16c[16] = {
    0.0f, 0.195090322016128268f, 0.382683432365089772f, 0.555570233019602225f,
    0.707106781186547524f, 0.831469612302545237f, 0.923879532511286756f,
    0.980785280403230449f, 1.0f, 0.980785280403230449f, 0.923879532511286756f,
    0.831469612302545237f, 0.707106781186547524f, 0.555570233019602225f,
    0.382683432365089772f, 0.195090322016128268f};

// generic radix-2 stage on 32 packed complex elements.
template<int H, int D, bool INV, bool B0>
__device__ __forceinline__ void bf32(u64* X, int base_eff) {
    const int S = D * H;
    const float coef = (INV ? PI_F : -PI_F) / (float)S;
    float w0s, w0c;
    if (B0) { w0c = 1.0f; w0s = 0.0f; }
    else    { __sincosf(coef * (float)base_eff, &w0s, &w0c); }

    #pragma unroll
    for (int k = 0; k < H; ++k) {
        const int t = k * (16 / H);
        const float ckr = C16c[t];
        const float cki = INV ? S16c[t] : -S16c[t];
        const float wc = B0 ? ckr : (w0c * ckr - w0s * cki);
        const float ws = B0 ? cki : (w0s * ckr + w0c * cki);
        const u64 wcc = pk(wc, wc);
        const u64 wss = pk(-ws, ws);
        #pragma unroll
        for (int g = 0; g < 32 / (2 * H); ++g) {
            const int j  = g * 2 * H + k;
            const int j2 = j + H;
            if (!INV) {
                u64 s = f2add(X[j], X[j2]);
                u64 d = f2sub(X[j], X[j2]);
                X[j] = s;
                if (B0 && t == 0)      X[j2] = d;
                else if (B0 && t == 8) X[j2] = f2mul(swp(d), pk(1.0f, -1.0f));  // w = -i
                else                   X[j2] = cmul(d, wcc, wss);
            } else {
                u64 tt;
                if (B0 && t == 0)      tt = X[j2];
                else if (B0 && t == 8) tt = f2mul(swp(X[j2]), pk(-1.0f, 1.0f)); // w = +i
                else                   tt = cmul(X[j2], wcc, wss);
                X[j2] = f2sub(X[j], tt);
                X[j]  = f2add(X[j], tt);
            }
        }
    }
}

// first forward stage (H=16, D=32) with X[16..31] == 0
__device__ __forceinline__ void bf32_first(u64* X, int base_eff) {
    const float coef = -PI_F / 512.0f;
    float w0s, w0c;
    __sincosf(coef * (float)base_eff, &w0s, &w0c);
    #pragma unroll
    for (int k = 0; k < 16; ++k) {
        const float ckr = C16c[k];
        const float cki = -S16c[k];
        const float wc = w0c * ckr - w0s * cki;
        const float ws = w0s * ckr + w0c * cki;
        X[k + 16] = cmul(X[k], pk(wc, wc), pk(-ws, ws));
    }
}

// last inverse stage (H=16, D=32): only X[0..15] survive
__device__ __forceinline__ void bf32_last(u64* X, int base_eff) {
    const float coef = PI_F / 512.0f;
    float w0s, w0c;
    __sincosf(coef * (float)base_eff, &w0s, &w0c);
    #pragma unroll
    for (int k = 0; k < 16; ++k) {
        const float ckr = C16c[k];
        const float cki = S16c[k];
        const float wc = w0c * ckr - w0s * cki;
        const float ws = w0s * ckr + w0c * cki;
        u64 tt = cmul(X[k + 16], pk(wc, wc), pk(-ws, ws));
        X[k] = f2add(X[k], tt);
    }
}

// ---- cp.async 16B into shared ----
__device__ __forceinline__ void cp16(float* dst, const float* src) {
    unsigned d = (unsigned)__cvta_generic_to_shared(dst);
    asm volatile("cp.async.ca.shared.global [%0], [%1], 16;" :: "r"(d), "l"(src));
}

// Stage the input of tile (bc, a0): stage[s*8 + row] = x_re, +4096 for x_im.
// 1024 chunks of 32B (512 re + 512 im); 256 threads x 4 chunks x 2 cp.async.
__device__ __forceinline__ void fill_stage(float* stage, const float* x,
                                           int bc, int a0, int tid) {
    #pragma unroll
    for (int k = 0; k < 4; ++k) {
        int c = tid + NTHREADS * k;          // 0..1023
        int s = c & 511;
        const float* src = x + (size_t)(bc + (c >> 9) * 8) * 262144 + a0 + s * 512;
        float* dst = stage + c * 8;
        cp16(dst, src);
        cp16(dst + 4, src + 4);
    }
    asm volatile("cp.async.commit_group;");
}

// Persistent: 296 CTAs, CTA b processes tiles t = b, b+296 (< 512).
// One tile: 8 packed complex rows (real rows bi, bi+4096; bi = bc*512 + a0 + row).
// Phase A/A2 mapping rowL=tid&7, rL=tid>>3; 20 stages in registers; two smem
// transposes per tile. Next tile's input prefetched via cp.async during C/A2.
__global__ void __launch_bounds__(NTHREADS, 2)
fbp_kernel(const float* __restrict__ x, const float* __restrict__ filt,
           float* __restrict__ out)
{
    extern __shared__ float2 sm2[];
    u64*   __restrict__ sm    = reinterpret_cast<u64*>(sm2);
    float* __restrict__ stage = reinterpret_cast<float*>(sm + 8 * PLANEW);

    const int tid = threadIdx.x;
    const int b   = blockIdx.x;

    const int rowL = tid & 7;
    const int rL   = tid >> 3;
    const int bAL  = rowL * PLANEW + rL;     // + 34j
    const int w    = tid >> 5;
    const int r    = tid & 31;
    const int bC   = w * PLANEW + 34 * r;    // 16B aligned

    u64 X[32];

    // prologue: stage first tile's input
    fill_stage(stage, x, b >> 6, (b & 63) << 3, tid);
    asm volatile("cp.async.wait_group 0;");
    __syncthreads();

    for (int t = b; t < NTILES; t += GRIDSZ) {
        const int bc = t >> 6;
        const int a0 = (t & 63) << 3;

        // ==== phase A: staging -> regs, fwd strides 512..32, store planes ====
        #pragma unroll
        for (int j = 0; j < 16; ++j) {
            int fi = (rL + 32 * j) * 8 + rowL;
            X[j] = pk(stage[fi], stage[4096 + fi]);
        }
        bf32_first(X, rL);
        bf32< 8, 32, false, false>(X, rL);
        bf32< 4, 32, false, false>(X, rL);
        bf32< 2, 32, false, false>(X, rL);
        bf32< 1, 32, false, false>(X, rL);
        #pragma unroll
        for (int j = 0; j < 32; ++j) sm[bAL + 34 * j] = X[j];
        __syncthreads();   // planes published; staging fully consumed

        // prefetch next tile's input into staging (overlaps phases C + A2)
        const int tn = t + GRIDSZ;
        if (tn < NTILES)
            fill_stage(stage, x, tn >> 6, (tn & 63) << 3, tid);

        // ==== phase C: fwd 16..1, filter, inv 1..16 ====
        {
            const ulonglong2* __restrict__ cp =
                reinterpret_cast<const ulonglong2*>(sm + bC);
            #pragma unroll
            for (int h = 0; h < 16; ++h) {
                ulonglong2 v = cp[h];
                X[2*h] = v.x; X[2*h+1] = v.y;
            }
        }
        bf32<16, 1, false, true>(X, 0);
        bf32< 8, 1, false, true>(X, 0);
        bf32< 4, 1, false, true>(X, 0);
        bf32< 2, 1, false, true>(X, 0);
        bf32< 1, 1, false, true>(X, 0);
        {
            const float4* __restrict__ f4 =
                reinterpret_cast<const float4*>(filt + 32 * r);
            #pragma unroll
            for (int i = 0; i < 8; ++i) {
                float4 f = __ldg(f4 + i);
                X[4*i+0] = f2mul(X[4*i+0], pk(f.x*(1.0f/1024.0f), f.x*(1.0f/1024.0f)));
                X[4*i+1] = f2mul(X[4*i+1], pk(f.y*(1.0f/1024.0f), f.y*(1.0f/1024.0f)));
                X[4*i+2] = f2mul(X[4*i+2], pk(f.z*(1.0f/1024.0f), f.z*(1.0f/1024.0f)));
                X[4*i+3] = f2mul(X[4*i+3], pk(f.w*(1.0f/1024.0f), f.w*(1.0f/1024.0f)));
            }
        }
        bf32< 1, 1, true, true>(X, 0);
        bf32< 2, 1, true, true>(X, 0);
        bf32< 4, 1, true, true>(X, 0);
        bf32< 8, 1, true, true>(X, 0);
        bf32<16, 1, true, true>(X, 0);
        {
            ulonglong2* __restrict__ cp = reinterpret_cast<ulonglong2*>(sm + bC);
            #pragma unroll
            for (int h = 0; h < 16; ++h) {
                ulonglong2 v; v.x = X[2*h]; v.y = X[2*h+1];
                cp[h] = v;
            }
        }
        __syncthreads();

        // ==== phase A2: inv strides 32..512, store to global ====
        #pragma unroll
        for (int j = 0; j < 32; ++j) X[j] = sm[bAL + 34 * j];
        bf32< 1, 32, true, false>(X, rL);
        bf32< 2, 32, true, false>(X, rL);
        bf32< 4, 32, true, false>(X, rL);
        bf32< 8, 32, true, false>(X, rL);
        bf32_last(X, rL);
        {
            float* __restrict__ ore = out + bc * 512 + a0 + rowL;
            float* __restrict__ oim = out + (bc + 8) * 512 + a0 + rowL;
            #pragma unroll
            for (int j = 0; j < 16; ++j) {
                float2 v = upk(X[j]);
                ore[(rL + 32 * j) * 8192] = v.x;
                oim[(rL + 32 * j) * 8192] = v.y;
            }
        }

        // staging for tn ready before next iteration's phase A
        if (tn < NTILES)
            asm volatile("cp.async.wait_group 0;");
        __syncthreads();   // protects planes reuse + publishes staging
    }
}

extern "C" void kernel_launch(void* const* d_in, const int* in_sizes, int n_in,
                              void* d_out, int out_size) {
    (void)in_sizes; (void)n_in; (void)out_size;
    const float* x    = (const float*)d_in[0];
    const float* filt = (const float*)d_in[3];   // fourier_filter_br
    float* out = (float*)d_out;

    const size_t smem_bytes = (size_t)8 * PLANEW * sizeof(u64)   // planes 69760
                            + (size_t)8192 * sizeof(float);      // staging 32768
    cudaFuncSetAttribute(fbp_kernel, cudaFuncAttributeMaxDynamicSharedMemorySize,
                         (int)smem_bytes);
    fbp_kernel<<<GRIDSZ, NTHREADS, smem_bytes>>>(x, filt, out);
}

// round 13
// speedup vs baseline: 1.2514x; 1.2514x over previous
#include <cuda_runtime.h>

#define PLANEW   1090            // u64 words per plane: 34*32=1088 +2; 1090 % 16 == 2
#define NTHREADS 256
#define NTILES   512
#define GRIDSZ   296             // 2 x 148: every SM holds exactly 2 CTAs
#define PI_F     3.14159265358979323846f

typedef unsigned long long u64;

// ---- packed f32x2 helpers (sm_100+ PTX; ptxas never emits these from C++) ----
__device__ __forceinline__ u64 pk(float a, float b) {
    u64 r; asm("mov.b64 %0, {%1, %2};" : "=l"(r) : "f"(a), "f"(b)); return r;
}
__device__ __forceinline__ float2 upk(u64 v) {
    float2 r; asm("mov.b64 {%0, %1}, %2;" : "=f"(r.x), "=f"(r.y) : "l"(v)); return r;
}
__device__ __forceinline__ u64 swp(u64 v) {
    u64 r;
    asm("{\n\t.reg .b32 lo, hi;\n\tmov.b64 {lo, hi}, %1;\n\tmov.b64 %0, {hi, lo};\n\t}"
        : "=l"(r) : "l"(v));
    return r;
}
__device__ __forceinline__ u64 f2add(u64 a, u64 b) {
    u64 r; asm("add.rn.f32x2 %0, %1, %2;" : "=l"(r) : "l"(a), "l"(b)); return r;
}
__device__ __forceinline__ u64 f2sub(u64 a, u64 b) {
    u64 r; asm("sub.rn.f32x2 %0, %1, %2;" : "=l"(r) : "l"(a), "l"(b)); return r;
}
__device__ __forceinline__ u64 f2mul(u64 a, u64 b) {
    u64 r; asm("mul.rn.f32x2 %0, %1, %2;" : "=l"(r) : "l"(a), "l"(b)); return r;
}
__device__ __forceinline__ u64 f2fma(u64 a, u64 b, u64 c) {
    u64 r; asm("fma.rn.f32x2 %0, %1, %2, %3;" : "=l"(r) : "l"(a), "l"(b), "l"(c)); return r;
}
__device__ __forceinline__ u64 cmul(u64 d, u64 wcc, u64 wss) {
    return f2fma(swp(d), wss, f2mul(d, wcc));
}
__device__ __forceinline__ void pfL2(const float* p) {
    asm volatile("prefetch.global.L2 [%0];" :: "l"(p));
}

__device__ __constant__ float C16c[16] = {
    1.0f, 0.980785280403230449f, 0.923879532511286756f, 0.831469612302545237f,
    0.707106781186547524f, 0.555570233019602225f, 0.382683432365089772f,
    0.195090322016128268f, 0.0f, -0.195090322016128268f, -0.382683432365089772f,
    -0.555570233019602225f, -0.707106781186547524f, -0.831469612302545237f,
    -0.923879532511286756f, -0.980785280403230449f};
__device__ __constant__ float S16c[16] = {
    0.0f, 0.195090322016128268f, 0.382683432365089772f, 0.555570233019602225f,
    0.707106781186547524f, 0.831469612302545237f, 0.923879532511286756f,
    0.980785280403230449f, 1.0f, 0.980785280403230449f, 0.923879532511286756f,
    0.831469612302545237f, 0.707106781186547524f, 0.555570233019602225f,
    0.382683432365089772f, 0.195090322016128268f};

// generic radix-2 stage on 32 packed complex elements.
template<int H, int D, bool INV, bool B0>
__device__ __forceinline__ void bf32(u64* X, int base_eff) {
    const int S = D * H;
    const float coef = (INV ? PI_F : -PI_F) / (float)S;
    float w0s, w0c;
    if (B0) { w0c = 1.0f; w0s = 0.0f; }
    else    { __sincosf(coef * (float)base_eff, &w0s, &w0c); }

    #pragma unroll
    for (int k = 0; k < H; ++k) {
        const int t = k * (16 / H);
        const float ckr = C16c[t];
        const float cki = INV ? S16c[t] : -S16c[t];
        const float wc = B0 ? ckr : (w0c * ckr - w0s * cki);
        const float ws = B0 ? cki : (w0s * ckr + w0c * cki);
        const u64 wcc = pk(wc, wc);
        const u64 wss = pk(-ws, ws);
        #pragma unroll
        for (int g = 0; g < 32 / (2 * H); ++g) {
            const int j  = g * 2 * H + k;
            const int j2 = j + H;
            if (!INV) {
                u64 s = f2add(X[j], X[j2]);
                u64 d = f2sub(X[j], X[j2]);
                X[j] = s;
                if (B0 && t == 0)      X[j2] = d;
                else if (B0 && t == 8) X[j2] = f2mul(swp(d), pk(1.0f, -1.0f));  // w = -i
                else                   X[j2] = cmul(d, wcc, wss);
            } else {
                u64 tt;
                if (B0 && t == 0)      tt = X[j2];
                else if (B0 && t == 8) tt = f2mul(swp(X[j2]), pk(-1.0f, 1.0f)); // w = +i
                else                   tt = cmul(X[j2], wcc, wss);
                X[j2] = f2sub(X[j], tt);
                X[j]  = f2add(X[j], tt);
            }
        }
    }
}

// first forward stage (H=16, D=32) with X[16..31] == 0
__device__ __forceinline__ void bf32_first(u64* X, int base_eff) {
    const float coef = -PI_F / 512.0f;
    float w0s, w0c;
    __sincosf(coef * (float)base_eff, &w0s, &w0c);
    #pragma unroll
    for (int k = 0; k < 16; ++k) {
        const float ckr = C16c[k];
        const float cki = -S16c[k];
        const float wc = w0c * ckr - w0s * cki;
        const float ws = w0s * ckr + w0c * cki;
        X[k + 16] = cmul(X[k], pk(wc, wc), pk(-ws, ws));
    }
}

// last inverse stage (H=16, D=32): only X[0..15] survive
__device__ __forceinline__ void bf32_last(u64* X, int base_eff) {
    const float coef = PI_F / 512.0f;
    float w0s, w0c;
    __sincosf(coef * (float)base_eff, &w0s, &w0c);
    #pragma unroll
    for (int k = 0; k < 16; ++k) {
        const float ckr = C16c[k];
        const float cki = S16c[k];
        const float wc = w0c * ckr - w0s * cki;
        const float ws = w0s * ckr + w0c * cki;
        u64 tt = cmul(X[k + 16], pk(wc, wc), pk(-ws, ws));
        X[k] = f2add(X[k], tt);
    }
}

// Persistent over <=2 tiles: CTA b handles t = b, b+296.  One tile: 8 packed
// complex rows (real rows bi, bi+4096; bi = bc*512 + a0 + row).  Phase A/A2
// mapping rowL=tid&7, rL=tid>>3 (warp global ops = 4 full 32B sectors); 20
// stages in registers; TWO smem transposes.  Next tile's input L2-prefetched
// during phases C/A2 (no regs, no smem, no waits).
// Plane layout word(p) = 34*(p>>5) + (p&31):
//   A access: word = rowL*PLANEW + rL + 34j   (LDS/STS.64, conflict-free)
//   C access: word = w*PLANEW + 34r + j       (LDS/STS.128, conflict-free)
__global__ void __launch_bounds__(NTHREADS, 2)
fbp_kernel(const float* __restrict__ x, const float* __restrict__ filt,
           float* __restrict__ out)
{
    extern __shared__ float2 sm2[];
    u64* __restrict__ sm = reinterpret_cast<u64*>(sm2);

    const int tid = threadIdx.x;
    const int b   = blockIdx.x;

    const int rowL = tid & 7;    // a-offset within tile
    const int rL   = tid >> 3;   // 0..31
    const int bAL  = rowL * PLANEW + rL;     // + 34j
    const int w    = tid >> 5;
    const int r    = tid & 31;
    const int bC   = w * PLANEW + 34 * r;    // 16B aligned (34r even)

    u64 X[32];

    for (int t = b; t < NTILES; t += GRIDSZ) {
        const int bc = t >> 6;
        const int a0 = (t & 63) << 3;

        // ==== phase A: direct global load + fwd strides 512..32 ====
        {
            const float* __restrict__ xre = x + bc * 262144 + a0 + rowL;
            const float* __restrict__ xim = x + (bc + 8) * 262144 + a0 + rowL;
            #pragma unroll
            for (int j = 0; j < 16; ++j) {   // p = rL + 32j < 512
                float vr = __ldg(xre + (rL + 32 * j) * 512);
                float vi = __ldg(xim + (rL + 32 * j) * 512);
                X[j] = pk(vr, vi);
            }
        }
        bf32_first(X, rL);
        bf32< 8, 32, false, false>(X, rL);
        bf32< 4, 32, false, false>(X, rL);
        bf32< 2, 32, false, false>(X, rL);
        bf32< 1, 32, false, false>(X, rL);
        #pragma unroll
        for (int j = 0; j < 32; ++j) sm[bAL + 34 * j] = X[j];
        __syncthreads();

        // L2-prefetch the NEXT tile's input (overlaps phases C + A2)
        const int tn = t + GRIDSZ;
        if (tn < NTILES) {
            const int bcn = tn >> 6;
            const int a0n = (tn & 63) << 3;
            const float* __restrict__ pre = x + bcn * 262144 + a0n + rowL;
            const float* __restrict__ pim = x + (bcn + 8) * 262144 + a0n + rowL;
            #pragma unroll
            for (int j = 0; j < 16; ++j) {
                pfL2(pre + (rL + 32 * j) * 512);
                pfL2(pim + (rL + 32 * j) * 512);
            }
        }

        // ==== phase C: fwd 16..1, filter, inv 1..16 ====
        {
            const ulonglong2* __restrict__ cp =
                reinterpret_cast<const ulonglong2*>(sm + bC);
            #pragma unroll
            for (int h = 0; h < 16; ++h) {
                ulonglong2 v = cp[h];
                X[2*h] = v.x; X[2*h+1] = v.y;
            }
        }
        bf32<16, 1, false, true>(X, 0);
        bf32< 8, 1, false, true>(X, 0);
        bf32< 4, 1, false, true>(X, 0);
        bf32< 2, 1, false, true>(X, 0);
        bf32< 1, 1, false, true>(X, 0);
        {
            const float4* __restrict__ f4 =
                reinterpret_cast<const float4*>(filt + 32 * r);
            #pragma unroll
            for (int i = 0; i < 8; ++i) {   // bit-reversed-domain filter; fold 1/n
                float4 f = __ldg(f4 + i);
                X[4*i+0] = f2mul(X[4*i+0], pk(f.x*(1.0f/1024.0f), f.x*(1.0f/1024.0f)));
                X[4*i+1] = f2mul(X[4*i+1], pk(f.y*(1.0f/1024.0f), f.y*(1.0f/1024.0f)));
                X[4*i+2] = f2mul(X[4*i+2], pk(f.z*(1.0f/1024.0f), f.z*(1.0f/1024.0f)));
                X[4*i+3] = f2mul(X[4*i+3], pk(f.w*(1.0f/1024.0f), f.w*(1.0f/1024.0f)));
            }
        }
        bf32< 1, 1, true, true>(X, 0);
        bf32< 2, 1, true, true>(X, 0);
        bf32< 4, 1, true, true>(X, 0);
        bf32< 8, 1, true, true>(X, 0);
        bf32<16, 1, true, true>(X, 0);
        {
            ulonglong2* __restrict__ cp = reinterpret_cast<ulonglong2*>(sm + bC);
            #pragma unroll
            for (int h = 0; h < 16; ++h) {
                ulonglong2 v; v.x = X[2*h]; v.y = X[2*h+1];
                cp[h] = v;
            }
        }
        __syncthreads();

        // ==== phase A2: inv strides 32..512 + direct global store ====
        #pragma unroll
        for (int j = 0; j < 32; ++j) X[j] = sm[bAL + 34 * j];
        bf32< 1, 32, true, false>(X, rL);
        bf32< 2, 32, true, false>(X, rL);
        bf32< 4, 32, true, false>(X, rL);
        bf32< 8, 32, true, false>(X, rL);
        bf32_last(X, rL);
        {
            // emit p = rL + 32j, j<16: out[p*8192 + bi], imag at bi+4096
            float* __restrict__ ore = out + bc * 512 + a0 + rowL;
            float* __restrict__ oim = out + (bc + 8) * 512 + a0 + rowL;
            #pragma unroll
            for (int j = 0; j < 16; ++j) {
                float2 v = upk(X[j]);
                ore[(rL + 32 * j) * 8192] = v.x;
                oim[(rL + 32 * j) * 8192] = v.y;
            }
        }

        if (tn < NTILES)
            __syncthreads();   // protect plane reuse before next phase A writes
    }
}

extern "C" void kernel_launch(void* const* d_in, const int* in_sizes, int n_in,
                              void* d_out, int out_size) {
    (void)in_sizes; (void)n_in; (void)out_size;
    const float* x    = (const float*)d_in[0];
    const float* filt = (const float*)d_in[3];   // fourier_filter_br
    float* out = (float*)d_out;

    const size_t smem_bytes = (size_t)8 * PLANEW * sizeof(u64);  // 69760
    cudaFuncSetAttribute(fbp_kernel, cudaFuncAttributeMaxDynamicSharedMemorySize,
                         (int)smem_bytes);
    fbp_kernel<<<GRIDSZ, NTHREADS, smem_bytes>>>(x, filt, out);
}

// round 14
// speedup vs baseline: 1.3908x; 1.1115x over previous
#include <cuda_runtime.h>

#define PLANEW   1090            // u64 words per plane: 34*32=1088 +2; 1090 % 16 == 2
#define NTHREADS 256
#define PI_F     3.14159265358979323846f

typedef unsigned long long u64;

// ---- packed f32x2 helpers (sm_100+ PTX; ptxas never emits these from C++) ----
__device__ __forceinline__ u64 pk(float a, float b) {
    u64 r; asm("mov.b64 %0, {%1, %2};" : "=l"(r) : "f"(a), "f"(b)); return r;
}
__device__ __forceinline__ float2 upk(u64 v) {
    float2 r; asm("mov.b64 {%0, %1}, %2;" : "=f"(r.x), "=f"(r.y) : "l"(v)); return r;
}
__device__ __forceinline__ u64 swp(u64 v) {
    u64 r;
    asm("{\n\t.reg .b32 lo, hi;\n\tmov.b64 {lo, hi}, %1;\n\tmov.b64 %0, {hi, lo};\n\t}"
        : "=l"(r) : "l"(v));
    return r;
}
__device__ __forceinline__ u64 f2add(u64 a, u64 b) {
    u64 r; asm("add.rn.f32x2 %0, %1, %2;" : "=l"(r) : "l"(a), "l"(b)); return r;
}
__device__ __forceinline__ u64 f2sub(u64 a, u64 b) {
    u64 r; asm("sub.rn.f32x2 %0, %1, %2;" : "=l"(r) : "l"(a), "l"(b)); return r;
}
__device__ __forceinline__ u64 f2mul(u64 a, u64 b) {
    u64 r; asm("mul.rn.f32x2 %0, %1, %2;" : "=l"(r) : "l"(a), "l"(b)); return r;
}
__device__ __forceinline__ u64 f2fma(u64 a, u64 b, u64 c) {
    u64 r; asm("fma.rn.f32x2 %0, %1, %2, %3;" : "=l"(r) : "l"(a), "l"(b), "l"(c)); return r;
}
__device__ __forceinline__ u64 cmul(u64 d, u64 wcc, u64 wss) {
    return f2fma(swp(d), wss, f2mul(d, wcc));
}

// streaming (evict-first) global access — x / out have zero in-kernel reuse
__device__ __forceinline__ float ldcs(const float* p) {
    float v; asm volatile("ld.global.cs.f32 %0, [%1];" : "=f"(v) : "l"(p)); return v;
}
__device__ __forceinline__ void stcs(float* p, float v) {
    asm volatile("st.global.cs.f32 [%0], %1;" :: "l"(p), "f"(v));
}
__device__ __forceinline__ float4 ldcs4(const float4* p) {
    float4 v;
    asm volatile("ld.global.cs.v4.f32 {%0,%1,%2,%3}, [%4];"
                 : "=f"(v.x), "=f"(v.y), "=f"(v.z), "=f"(v.w) : "l"(p));
    return v;
}

__device__ __constant__ float C16c[16] = {
    1.0f, 0.980785280403230449f, 0.923879532511286756f, 0.831469612302545237f,
    0.707106781186547524f, 0.555570233019602225f, 0.382683432365089772f,
    0.195090322016128268f, 0.0f, -0.195090322016128268f, -0.382683432365089772f,
    -0.555570233019602225f, -0.707106781186547524f, -0.831469612302545237f,
    -0.923879532511286756f, -0.980785280403230449f};
__device__ __constant__ float S16c[16] = {
    0.0f, 0.195090322016128268f, 0.382683432365089772f, 0.555570233019602225f,
    0.707106781186547524f, 0.831469612302545237f, 0.923879532511286756f,
    0.980785280403230449f, 1.0f, 0.980785280403230449f, 0.923879532511286756f,
    0.831469612302545237f, 0.707106781186547524f, 0.555570233019602225f,
    0.382683432365089772f, 0.195090322016128268f};

// generic radix-2 stage on 32 packed complex elements.
template<int H, int D, bool INV, bool B0>
__device__ __forceinline__ void bf32(u64* X, int base_eff) {
    const int S = D * H;
    const float coef = (INV ? PI_F : -PI_F) / (float)S;
    float w0s, w0c;
    if (B0) { w0c = 1.0f; w0s = 0.0f; }
    else    { __sincosf(coef * (float)base_eff, &w0s, &w0c); }

    #pragma unroll
    for (int k = 0; k < H; ++k) {
        const int t = k * (16 / H);
        const float ckr = C16c[t];
        const float cki = INV ? S16c[t] : -S16c[t];
        const float wc = B0 ? ckr : (w0c * ckr - w0s * cki);
        const float ws = B0 ? cki : (w0s * ckr + w0c * cki);
        const u64 wcc = pk(wc, wc);
        const u64 wss = pk(-ws, ws);
        #pragma unroll
        for (int g = 0; g < 32 / (2 * H); ++g) {
            const int j  = g * 2 * H + k;
            const int j2 = j + H;
            if (!INV) {
                u64 s = f2add(X[j], X[j2]);
                u64 d = f2sub(X[j], X[j2]);
                X[j] = s;
                if (B0 && t == 0)      X[j2] = d;
                else if (B0 && t == 8) X[j2] = f2mul(swp(d), pk(1.0f, -1.0f));  // w = -i
                else                   X[j2] = cmul(d, wcc, wss);
            } else {
                u64 tt;
                if (B0 && t == 0)      tt = X[j2];
                else if (B0 && t == 8) tt = f2mul(swp(X[j2]), pk(-1.0f, 1.0f)); // w = +i
                else                   tt = cmul(X[j2], wcc, wss);
                X[j2] = f2sub(X[j], tt);
                X[j]  = f2add(X[j], tt);
            }
        }
    }
}

// first forward stage (H=16, D=32) with X[16..31] == 0
__device__ __forceinline__ void bf32_first(u64* X, int base_eff) {
    const float coef = -PI_F / 512.0f;
    float w0s, w0c;
    __sincosf(coef * (float)base_eff, &w0s, &w0c);
    #pragma unroll
    for (int k = 0; k < 16; ++k) {
        const float ckr = C16c[k];
        const float cki = -S16c[k];
        const float wc = w0c * ckr - w0s * cki;
        const float ws = w0s * ckr + w0c * cki;
        X[k + 16] = cmul(X[k], pk(wc, wc), pk(-ws, ws));
    }
}

// last inverse stage (H=16, D=32): only X[0..15] survive
__device__ __forceinline__ void bf32_last(u64* X, int base_eff) {
    const float coef = PI_F / 512.0f;
    float w0s, w0c;
    __sincosf(coef * (float)base_eff, &w0s, &w0c);
    #pragma unroll
    for (int k = 0; k < 16; ++k) {
        const float ckr = C16c[k];
        const float cki = S16c[k];
        const float wc = w0c * ckr - w0s * cki;
        const float ws = w0s * ckr + w0c * cki;
        u64 tt = cmul(X[k + 16], pk(wc, wc), pk(-ws, ws));
        X[k] = f2add(X[k], tt);
    }
}

// One CTA = one tile: 8 packed complex rows (real rows bi, bi+4096;
// bi = bc*512 + a0 + row).  Phase A/A2 mapping rowL=tid&7, rL=tid>>3 (warp
// global ops = 4 full 32B sectors); 20 stages in registers; TWO smem
// transposes.  Plane layout word(p) = 34*(p>>5) + (p&31):
//   A access: word = rowL*PLANEW + rL + 34j   (LDS/STS.64, conflict-free)
//   C access: word = w*PLANEW + 34r + j       (LDS/STS.128, conflict-free)
__global__ void __launch_bounds__(NTHREADS, 2)
fbp_kernel(const float* __restrict__ x, const float* __restrict__ filt,
           float* __restrict__ out)
{
    extern __shared__ float2 sm2[];
    u64* __restrict__ sm = reinterpret_cast<u64*>(sm2);

    const int tid = threadIdx.x;
    const int bc  = blockIdx.x >> 6;         // 0..7
    const int a0  = (blockIdx.x & 63) << 3;  // 0..504 step 8

    const int rowL = tid & 7;    // a-offset within tile
    const int rL   = tid >> 3;   // 0..31
    const int bAL  = rowL * PLANEW + rL;     // + 34j
    const int w    = tid >> 5;
    const int r    = tid & 31;
    const int bC   = w * PLANEW + 34 * r;    // 16B aligned (34r even)

    u64 X[32];

    // ======== phase A: direct global load (streaming) + fwd strides 512..32 ====
    {
        const float* __restrict__ xre = x + bc * 262144 + a0 + rowL;
        const float* __restrict__ xim = x + (bc + 8) * 262144 + a0 + rowL;
        #pragma unroll
        for (int j = 0; j < 16; ++j) {   // p = rL + 32j < 512
            float vr = ldcs(xre + (rL + 32 * j) * 512);
            float vi = ldcs(xim + (rL + 32 * j) * 512);
            X[j] = pk(vr, vi);
        }
    }
    bf32_first(X, rL);
    bf32< 8, 32, false, false>(X, rL);
    bf32< 4, 32, false, false>(X, rL);
    bf32< 2, 32, false, false>(X, rL);
    bf32< 1, 32, false, false>(X, rL);
    #pragma unroll
    for (int j = 0; j < 32; ++j) sm[bAL + 34 * j] = X[j];
    __syncthreads();

    // ======== phase C: fwd 16..1, filter, inv 1..16 ========
    // hoist filter loads so their latency overlaps LDS + first stages
    float4 f0, f1, f2, f3, f4v, f5, f6, f7;
    {
        const float4* __restrict__ fp = reinterpret_cast<const float4*>(filt + 32 * r);
        f0 = __ldg(fp + 0); f1 = __ldg(fp + 1); f2 = __ldg(fp + 2); f3 = __ldg(fp + 3);
        f4v = __ldg(fp + 4); f5 = __ldg(fp + 5); f6 = __ldg(fp + 6); f7 = __ldg(fp + 7);
    }
    {
        const ulonglong2* __restrict__ cp =
            reinterpret_cast<const ulonglong2*>(sm + bC);
        #pragma unroll
        for (int h = 0; h < 16; ++h) {
            ulonglong2 v = cp[h];
            X[2*h] = v.x; X[2*h+1] = v.y;
        }
    }
    bf32<16, 1, false, true>(X, 0);
    bf32< 8, 1, false, true>(X, 0);
    bf32< 4, 1, false, true>(X, 0);
    bf32< 2, 1, false, true>(X, 0);
    bf32< 1, 1, false, true>(X, 0);
    {
        const float4 ff[8] = {f0, f1, f2, f3, f4v, f5, f6, f7};
        #pragma unroll
        for (int i = 0; i < 8; ++i) {   // bit-reversed-domain filter; fold 1/n
            X[4*i+0] = f2mul(X[4*i+0], pk(ff[i].x*(1.0f/1024.0f), ff[i].x*(1.0f/1024.0f)));
            X[4*i+1] = f2mul(X[4*i+1], pk(ff[i].y*(1.0f/1024.0f), ff[i].y*(1.0f/1024.0f)));
            X[4*i+2] = f2mul(X[4*i+2], pk(ff[i].z*(1.0f/1024.0f), ff[i].z*(1.0f/1024.0f)));
            X[4*i+3] = f2mul(X[4*i+3], pk(ff[i].w*(1.0f/1024.0f), ff[i].w*(1.0f/1024.0f)));
        }
    }
    bf32< 1, 1, true, true>(X, 0);
    bf32< 2, 1, true, true>(X, 0);
    bf32< 4, 1, true, true>(X, 0);
    bf32< 8, 1, true, true>(X, 0);
    bf32<16, 1, true, true>(X, 0);
    {
        ulonglong2* __restrict__ cp = reinterpret_cast<ulonglong2*>(sm + bC);
        #pragma unroll
        for (int h = 0; h < 16; ++h) {
            ulonglong2 v; v.x = X[2*h]; v.y = X[2*h+1];
            cp[h] = v;
        }
    }
    __syncthreads();

    // ======== phase A2: inv strides 32..512 + direct global store (streaming) ==
    #pragma unroll
    for (int j = 0; j < 32; ++j) X[j] = sm[bAL + 34 * j];
    bf32< 1, 32, true, false>(X, rL);
    bf32< 2, 32, true, false>(X, rL);
    bf32< 4, 32, true, false>(X, rL);
    bf32< 8, 32, true, false>(X, rL);
    bf32_last(X, rL);
    {
        // emit p = rL + 32j, j<16: out[p*8192 + bi], imag at bi+4096
        float* __restrict__ ore = out + bc * 512 + a0 + rowL;
        float* __restrict__ oim = out + (bc + 8) * 512 + a0 + rowL;
        #pragma unroll
        for (int j = 0; j < 16; ++j) {
            float2 v = upk(X[j]);
            stcs(ore + (rL + 32 * j) * 8192, v.x);
            stcs(oim + (rL + 32 * j) * 8192, v.y);
        }
    }
}

extern "C" void kernel_launch(void* const* d_in, const int* in_sizes, int n_in,
                              void* d_out, int out_size) {
    (void)in_sizes; (void)n_in; (void)out_size;
    const float* x    = (const float*)d_in[0];
    const float* filt = (const float*)d_in[3];   // fourier_filter_br
    float* out = (float*)d_out;

    const size_t smem_bytes = (size_t)8 * PLANEW * sizeof(u64);  // 69760
    cudaFuncSetAttribute(fbp_kernel, cudaFuncAttributeMaxDynamicSharedMemorySize,
                         (int)smem_bytes);
    fbp_kernel<<<512, NTHREADS, smem_bytes>>>(x, filt, out);
}